// round 15
// baseline (speedup 1.0000x reference)
#include <cuda_runtime.h>
#include <cstdio>
#include <cstdint>

#define DIM   2048
#define NQ    11
#define MASKV (DIM - 1)
#define MASK2 (DIM * DIM - 1)

// ---------------- static scratch ----------------
__device__ float2 d_B[DIM * DIM];      // B = Xc U^H, then y (in place)
__device__ float2 d_gates[5 * NQ * 4]; // fused gate per (layer,qubit)

// ---------------- complex helpers ----------------
__device__ __forceinline__ float2 cmul(float2 a, float2 b) {
    return make_float2(fmaf(a.x, b.x, -a.y * b.y), fmaf(a.x, b.y, a.y * b.x));
}
__device__ __forceinline__ float2 cfma(float2 a, float2 b, float2 c) { // a*b + c
    return make_float2(fmaf(a.x, b.x, fmaf(-a.y, b.y, c.x)),
                       fmaf(a.x, b.y, fmaf( a.y, b.x, c.y)));
}
__device__ __forceinline__ void bfly(float2 g0, float2 g1, float2 g2, float2 g3,
                                     float2& v0, float2& v1) {
    float2 n0 = cfma(g0, v0, cmul(g1, v1));
    float2 n1 = cfma(g2, v0, cmul(g3, v1));
    v0 = n0; v1 = n1;
}

// ---------------- precompute fused gates ----------------
__global__ void precompute_kernel(const float* __restrict__ w, int ok) {
    int tid = threadIdx.x;
    if (tid >= 5 * NQ) return;
    float2* g = &d_gates[tid * 4];
    if (!ok || w == nullptr) {
        g[0] = make_float2(1.f, 0.f); g[1] = make_float2(0.f, 0.f);
        g[2] = make_float2(0.f, 0.f); g[3] = make_float2(1.f, 0.f);
        return;
    }
    int layer = tid / NQ, q = tid % NQ;
    const float WM = 0.6324555320336759f; // sqrt(2/5)
    float hx = w[3 * NQ * layer + q] * WM * 0.5f;            // max idx 164 (<165)
    float hy = w[3 * NQ * layer + NQ + q] * WM * 0.5f;
    float hz = w[3 * NQ * layer + 2 * NQ + q] * WM * 0.5f;
    float cx = cosf(hx), sx = sinf(hx);
    float cy = cosf(hy), sy = sinf(hy);
    float cz = cosf(hz), sz = sinf(hz);
    // m = gy @ gx
    float2 m00 = make_float2( cy * cx,  sy * sx);
    float2 m01 = make_float2(-sy * cx, -cy * sx);
    float2 m10 = make_float2( sy * cx, -cy * sx);
    float2 m11 = make_float2( cy * cx, -sy * sx);
    float2 ezm = make_float2(cz, -sz); // e^{-i hz}
    float2 ezp = make_float2(cz,  sz); // e^{+i hz}
    g[0] = cmul(ezm, m00); g[1] = cmul(ezm, m01);
    g[2] = cmul(ezp, m10); g[3] = cmul(ezp, m11);
}

// ---------------- fused-2q circuit core (all smem indices masked) ----------------
__device__ __forceinline__ void run_circuit(float2* sv, const float2* sg, int tid) {
    int pidx[8];
    #pragma unroll
    for (int rep = 0; rep < 8; ++rep) {
        int x = tid + rep * 256;
        #pragma unroll
        for (int c = NQ - 1; c >= 0; --c) {
            int t = (c + 1) % NQ;
            x ^= ((x >> (NQ - 1 - c)) & 1) << (NQ - 1 - t);
        }
        pidx[rep] = x & MASKV;
    }

    for (int layer = 0; layer < 5; ++layer) {
        const float2* gl = &sg[layer * NQ * 4];
        #pragma unroll
        for (int q = 0; q < 10; q += 2) {
            const int ka = 10 - q;
            const int sa = 1 << ka;
            const int sb = sa >> 1;
            const float2 a0 = gl[q * 4 + 0], a1 = gl[q * 4 + 1],
                         a2 = gl[q * 4 + 2], a3 = gl[q * 4 + 3];
            const float2 b0 = gl[(q + 1) * 4 + 0], b1 = gl[(q + 1) * 4 + 1],
                         b2 = gl[(q + 1) * 4 + 2], b3 = gl[(q + 1) * 4 + 3];
            #pragma unroll
            for (int rep = 0; rep < 2; ++rep) {
                int p  = tid + rep * 256;
                int i0 = (((p >> (ka - 1)) << (ka + 1)) | (p & (sb - 1))) & MASKV;
                int iA = (i0 + sb) & MASKV;
                int iB = (i0 + sa) & MASKV;
                int iC = (i0 + sa + sb) & MASKV;
                float2 v0 = sv[i0], v1 = sv[iA], v2 = sv[iB], v3 = sv[iC];
                bfly(b0, b1, b2, b3, v0, v1);
                bfly(b0, b1, b2, b3, v2, v3);
                bfly(a0, a1, a2, a3, v0, v2);
                bfly(a0, a1, a2, a3, v1, v3);
                sv[i0] = v0; sv[iA] = v1; sv[iB] = v2; sv[iC] = v3;
            }
            __syncthreads();
        }
        {
            const float2 g0 = gl[40], g1 = gl[41], g2 = gl[42], g3 = gl[43];
            #pragma unroll
            for (int rep = 0; rep < 4; ++rep) {
                int i0 = ((tid + rep * 256) << 1) & MASKV;
                int i1 = (i0 + 1) & MASKV;
                float2 v0 = sv[i0], v1 = sv[i1];
                bfly(g0, g1, g2, g3, v0, v1);
                sv[i0] = v0; sv[i1] = v1;
            }
            __syncthreads();
        }
        if (layer < 4) {
            float2 tmp[8];
            #pragma unroll
            for (int rep = 0; rep < 8; ++rep) tmp[rep] = sv[pidx[rep]];
            __syncthreads();
            #pragma unroll
            for (int rep = 0; rep < 8; ++rep) sv[(tid + rep * 256) & MASKV] = tmp[rep];
            __syncthreads();
        }
    }
}

// ---------------- K1: B row k = conj(U) @ x_row_k -> d_B ----------------
__global__ void __launch_bounds__(256)
k1_rows(const float* __restrict__ x, long long xn) {
    __shared__ float2 sv[DIM];
    __shared__ float2 sg[5 * NQ * 4];
    const int tid = threadIdx.x;
    const int vec = blockIdx.x;

    for (int i = tid; i < 5 * NQ * 4; i += 256) {
        float2 g = d_gates[i];
        g.y = -g.y;                       // conj(U)
        sg[i] = g;
    }

    for (int i = tid; i < DIM; i += 256) {
        long long gi = (long long)vec * DIM + i;
        float re = (x != nullptr && gi < xn) ? x[gi] : 0.0f;   // bounded by real size
        sv[i] = make_float2(re, 0.0f);
    }
    __syncthreads();

    run_circuit(sv, sg, tid);

    for (int i = tid; i < DIM; i += 256)
        d_B[((size_t)vec * DIM + i) & MASK2] = sv[i];
}

// ---------------- K2: column j of d_B <- U @ B_col_j (in place, no overlap) ----------------
__global__ void __launch_bounds__(256)
k2_cols() {
    __shared__ float2 sv[DIM];
    __shared__ float2 sg[5 * NQ * 4];
    const int tid = threadIdx.x;
    const int col = blockIdx.x;

    for (int i = tid; i < 5 * NQ * 4; i += 256) sg[i] = d_gates[i]; // forward U

    for (int i = tid; i < DIM; i += 256)
        sv[i] = d_B[((size_t)i * DIM + col) & MASK2];
    __syncthreads();

    run_circuit(sv, sg, tid);

    for (int i = tid; i < DIM; i += 256)
        d_B[((size_t)i * DIM + col) & MASK2] = sv[i];
}

// ---------------- K3: real part -> d_out (float32, coalesced, <= out_size elems) ----------------
__global__ void __launch_bounds__(256)
k3_real(float* __restrict__ out, long long cap) {
    long long j = (long long)blockIdx.x * blockDim.x + threadIdx.x;
    long long stride = (long long)gridDim.x * blockDim.x;
    for (; j < cap; j += stride)
        out[j] = d_B[j & MASK2].x;
}

extern "C" void kernel_launch(void* const* d_in, const int* in_sizes, int n_in,
                              void* d_out, int out_size) {
    // Confirmed layout (R13 diag): one input has 4,194,304 elems (x), one has 165 (weight).
    const float* x = nullptr;  long long xn = 0;
    const float* w = nullptr;  int w_ok = 0;
    for (int i = 0; i < n_in; ++i) {
        if (in_sizes[i] >= DIM * DIM && !x) { x = (const float*)d_in[i]; xn = DIM * DIM; }
        else if (in_sizes[i] >= 15 * NQ && in_sizes[i] < DIM * DIM && !w) {
            w = (const float*)d_in[i]; w_ok = 1;
        }
    }

    // Output: out_size elements of FLOAT32 (real part) — never write beyond it.
    long long cap = (long long)out_size;
    if (cap > (long long)DIM * DIM) cap = (long long)DIM * DIM;

    precompute_kernel<<<1, 64>>>(w, w_ok);
    k1_rows<<<DIM, 256>>>(x, xn);       // d_B := B = Xc U^H (rows)
    k2_cols<<<DIM, 256>>>();            // d_B := y (in-place per column)
    k3_real<<<1024, 256>>>((float*)d_out, cap);   // out := real(y), 16 MB max

    fprintf(stderr, "[diag] issued: n_in=%d out_size=%d lasterr=%d\n",
            n_in, out_size, (int)cudaGetLastError());
    fflush(stderr);
}

// round 16
// speedup vs baseline: 1.0054x; 1.0054x over previous
#include <cuda_runtime.h>
#include <cstdint>

#define DIM   2048
#define NQ    11
#define MASKV (DIM - 1)
#define MASK2 (DIM * DIM - 1)

typedef unsigned long long u64;

// ---------------- static scratch ----------------
__device__ float2 d_B[DIM * DIM];      // B = Xc U^H, then y (in place)
__device__ float2 d_gates[5 * NQ * 4]; // fused gate per (layer,qubit)

// ---------------- packed f32x2 helpers ----------------
__device__ __forceinline__ u64 pk2(float s) {           // (s, s)
    u64 r; asm("mov.b64 %0, {%1, %1};" : "=l"(r) : "f"(s)); return r;
}
__device__ __forceinline__ u64 fma2(u64 a, u64 b, u64 c) { // a*b + c (per lane)
    u64 d; asm("fma.rn.f32x2 %0, %1, %2, %3;" : "=l"(d) : "l"(a), "l"(b), "l"(c));
    return d;
}
__device__ __forceinline__ u64 mul2(u64 a, u64 b) {
    u64 d; asm("mul.rn.f32x2 %0, %1, %2;" : "=l"(d) : "l"(a), "l"(b));
    return d;
}
__device__ __forceinline__ u64 swneg(u64 v) {           // (x,y) -> (-y, x)
    float x, y; asm("mov.b64 {%0, %1}, %2;" : "=f"(x), "=f"(y) : "l"(v));
    float ny = -y;
    u64 r; asm("mov.b64 %0, {%1, %2};" : "=l"(r) : "f"(ny), "f"(x)); return r;
}
__device__ __forceinline__ u64 f2u(float2 v) {
    u64 r; asm("mov.b64 %0, {%1, %2};" : "=l"(r) : "f"(v.x), "f"(v.y)); return r;
}
__device__ __forceinline__ float2 u2f(u64 v) {
    float2 r; asm("mov.b64 {%0, %1}, %2;" : "=f"(r.x), "=f"(r.y) : "l"(v)); return r;
}

// Packed 2x2 complex gate: duplicated scalar coefficients
struct PG {
    u64 x00, y00, x01, y01, x10, y10, x11, y11;
};
__device__ __forceinline__ PG make_pg(float2 g00, float2 g01, float2 g10, float2 g11) {
    PG p;
    p.x00 = pk2(g00.x); p.y00 = pk2(g00.y);
    p.x01 = pk2(g01.x); p.y01 = pk2(g01.y);
    p.x10 = pk2(g10.x); p.y10 = pk2(g10.y);
    p.x11 = pk2(g11.x); p.y11 = pk2(g11.y);
    return p;
}
// butterfly: (v0,v1) <- (g00*v0 + g01*v1, g10*v0 + g11*v1), complex via packed ops
__device__ __forceinline__ void bfly2(const PG& g, u64& v0, u64& v1) {
    u64 s0 = swneg(v0), s1 = swneg(v1);
    u64 n0 = fma2(g.x00, v0, fma2(g.y00, s0, fma2(g.x01, v1, mul2(g.y01, s1))));
    u64 n1 = fma2(g.x10, v0, fma2(g.y10, s0, fma2(g.x11, v1, mul2(g.y11, s1))));
    v0 = n0; v1 = n1;
}

// ---------------- complex helper (host-side gate build on device) ----------------
__device__ __forceinline__ float2 cmul(float2 a, float2 b) {
    return make_float2(fmaf(a.x, b.x, -a.y * b.y), fmaf(a.x, b.y, a.y * b.x));
}

// ---------------- precompute fused gates ----------------
__global__ void precompute_kernel(const float* __restrict__ w, int ok) {
    int tid = threadIdx.x;
    if (tid >= 5 * NQ) return;
    float2* g = &d_gates[tid * 4];
    if (!ok || w == nullptr) {
        g[0] = make_float2(1.f, 0.f); g[1] = make_float2(0.f, 0.f);
        g[2] = make_float2(0.f, 0.f); g[3] = make_float2(1.f, 0.f);
        return;
    }
    int layer = tid / NQ, q = tid % NQ;
    const float WM = 0.6324555320336759f; // sqrt(2/5)
    float hx = w[3 * NQ * layer + q] * WM * 0.5f;
    float hy = w[3 * NQ * layer + NQ + q] * WM * 0.5f;
    float hz = w[3 * NQ * layer + 2 * NQ + q] * WM * 0.5f;
    float cx = cosf(hx), sx = sinf(hx);
    float cy = cosf(hy), sy = sinf(hy);
    float cz = cosf(hz), sz = sinf(hz);
    // m = gy @ gx
    float2 m00 = make_float2( cy * cx,  sy * sx);
    float2 m01 = make_float2(-sy * cx, -cy * sx);
    float2 m10 = make_float2( sy * cx, -cy * sx);
    float2 m11 = make_float2( cy * cx, -sy * sx);
    float2 ezm = make_float2(cz, -sz); // e^{-i hz}
    float2 ezp = make_float2(cz,  sz); // e^{+i hz}
    g[0] = cmul(ezm, m00); g[1] = cmul(ezm, m01);
    g[2] = cmul(ezp, m10); g[3] = cmul(ezp, m11);
}

// ---------------- fused-2q circuit core (packed math, smem indices masked) ----------------
__device__ __forceinline__ void run_circuit(u64* sv, const float2* sg, int tid) {
    int pidx[8];
    #pragma unroll
    for (int rep = 0; rep < 8; ++rep) {
        int x = tid + rep * 256;
        #pragma unroll
        for (int c = NQ - 1; c >= 0; --c) {
            int t = (c + 1) % NQ;
            x ^= ((x >> (NQ - 1 - c)) & 1) << (NQ - 1 - t);
        }
        pidx[rep] = x & MASKV;
    }

    for (int layer = 0; layer < 5; ++layer) {
        const float2* gl = &sg[layer * NQ * 4];
        #pragma unroll
        for (int q = 0; q < 10; q += 2) {
            const int ka = 10 - q;
            const int sa = 1 << ka;
            const int sb = sa >> 1;
            const PG A = make_pg(gl[q*4+0], gl[q*4+1], gl[q*4+2], gl[q*4+3]);
            const PG B = make_pg(gl[(q+1)*4+0], gl[(q+1)*4+1], gl[(q+1)*4+2], gl[(q+1)*4+3]);
            #pragma unroll
            for (int rep = 0; rep < 2; ++rep) {
                int p  = tid + rep * 256;
                int i0 = (((p >> (ka - 1)) << (ka + 1)) | (p & (sb - 1))) & MASKV;
                int iA = (i0 + sb) & MASKV;
                int iB = (i0 + sa) & MASKV;
                int iC = (i0 + sa + sb) & MASKV;
                u64 v0 = sv[i0], v1 = sv[iA], v2 = sv[iB], v3 = sv[iC];
                bfly2(B, v0, v1);   // qubit q+1 (stride sb)
                bfly2(B, v2, v3);
                bfly2(A, v0, v2);   // qubit q   (stride sa)
                bfly2(A, v1, v3);
                sv[i0] = v0; sv[iA] = v1; sv[iB] = v2; sv[iC] = v3;
            }
            __syncthreads();
        }
        { // qubit 10, stride 1
            const PG G = make_pg(gl[40], gl[41], gl[42], gl[43]);
            #pragma unroll
            for (int rep = 0; rep < 4; ++rep) {
                int i0 = ((tid + rep * 256) << 1) & MASKV;
                int i1 = (i0 + 1) & MASKV;
                u64 v0 = sv[i0], v1 = sv[i1];
                bfly2(G, v0, v1);
                sv[i0] = v0; sv[i1] = v1;
            }
            __syncthreads();
        }
        if (layer < 4) { // ring of CNOTs = composed gather permutation
            u64 tmp[8];
            #pragma unroll
            for (int rep = 0; rep < 8; ++rep) tmp[rep] = sv[pidx[rep]];
            __syncthreads();
            #pragma unroll
            for (int rep = 0; rep < 8; ++rep) sv[(tid + rep * 256) & MASKV] = tmp[rep];
            __syncthreads();
        }
    }
}

// ---------------- K1: B row k = conj(U) @ x_row_k -> d_B ----------------
__global__ void __launch_bounds__(256)
k1_rows(const float* __restrict__ x, long long xn) {
    __shared__ u64   sv[DIM];
    __shared__ float2 sg[5 * NQ * 4];
    const int tid = threadIdx.x;
    const int vec = blockIdx.x;

    for (int i = tid; i < 5 * NQ * 4; i += 256) {
        float2 g = d_gates[i];
        g.y = -g.y;                       // conj(U)
        sg[i] = g;
    }

    for (int i = tid; i < DIM; i += 256) {
        long long gi = (long long)vec * DIM + i;
        float re = (x != nullptr && gi < xn) ? x[gi] : 0.0f;
        sv[i] = f2u(make_float2(re, 0.0f));
    }
    __syncthreads();

    run_circuit(sv, sg, tid);

    for (int i = tid; i < DIM; i += 256)
        d_B[((size_t)vec * DIM + i) & MASK2] = u2f(sv[i]);
}

// ---------------- K2: column j of d_B <- U @ B_col_j (in place) ----------------
__global__ void __launch_bounds__(256)
k2_cols() {
    __shared__ u64   sv[DIM];
    __shared__ float2 sg[5 * NQ * 4];
    const int tid = threadIdx.x;
    const int col = blockIdx.x;

    for (int i = tid; i < 5 * NQ * 4; i += 256) sg[i] = d_gates[i]; // forward U

    for (int i = tid; i < DIM; i += 256)
        sv[i] = f2u(d_B[((size_t)i * DIM + col) & MASK2]);
    __syncthreads();

    run_circuit(sv, sg, tid);

    for (int i = tid; i < DIM; i += 256)
        d_B[((size_t)i * DIM + col) & MASK2] = u2f(sv[i]);
}

// ---------------- K3: real part -> d_out (float32, coalesced) ----------------
__global__ void __launch_bounds__(256)
k3_real(float* __restrict__ out, long long cap) {
    long long j = (long long)blockIdx.x * blockDim.x + threadIdx.x;
    long long stride = (long long)gridDim.x * blockDim.x;
    for (; j < cap; j += stride)
        out[j] = d_B[j & MASK2].x;
}

extern "C" void kernel_launch(void* const* d_in, const int* in_sizes, int n_in,
                              void* d_out, int out_size) {
    const float* x = nullptr;  long long xn = 0;
    const float* w = nullptr;  int w_ok = 0;
    for (int i = 0; i < n_in; ++i) {
        if (in_sizes[i] >= DIM * DIM && !x) { x = (const float*)d_in[i]; xn = DIM * DIM; }
        else if (in_sizes[i] >= 15 * NQ && in_sizes[i] < DIM * DIM && !w) {
            w = (const float*)d_in[i]; w_ok = 1;
        }
    }

    long long cap = (long long)out_size;
    if (cap > (long long)DIM * DIM) cap = (long long)DIM * DIM;

    precompute_kernel<<<1, 64>>>(w, w_ok);
    k1_rows<<<DIM, 256>>>(x, xn);                 // d_B := B = Xc U^H (rows)
    k2_cols<<<DIM, 256>>>();                      // d_B := y (in-place per column)
    k3_real<<<1024, 256>>>((float*)d_out, cap);   // out := real(y)
}

// round 17
// speedup vs baseline: 1.1655x; 1.1592x over previous
#include <cuda_runtime.h>
#include <cstdint>

#define DIM   2048
#define NQ    11

typedef unsigned long long u64;

// ---------------- static scratch ----------------
__device__ float2 d_B[DIM * DIM];      // B = Xc U^H
__device__ float2 d_gates[5 * NQ * 4]; // fused gate per (layer,qubit)

// ---------------- packed f32x2 helpers ----------------
__device__ __forceinline__ u64 pkdup(float s) {          // (s, s)
    u64 r; asm("mov.b64 %0, {%1, %1};" : "=l"(r) : "f"(s)); return r;
}
__device__ __forceinline__ u64 pkni(float s) {           // (-s, s)
    float ns = -s;
    u64 r; asm("mov.b64 %0, {%1, %2};" : "=l"(r) : "f"(ns), "f"(s)); return r;
}
__device__ __forceinline__ u64 fma2(u64 a, u64 b, u64 c) {
    u64 d; asm("fma.rn.f32x2 %0, %1, %2, %3;" : "=l"(d) : "l"(a), "l"(b), "l"(c));
    return d;
}
__device__ __forceinline__ u64 mul2(u64 a, u64 b) {
    u64 d; asm("mul.rn.f32x2 %0, %1, %2;" : "=l"(d) : "l"(a), "l"(b));
    return d;
}
__device__ __forceinline__ u64 swap64(u64 v) {           // (x,y) -> (y,x)
    u64 r;
    asm("{ .reg .b32 xx, yy; mov.b64 {xx, yy}, %1; mov.b64 %0, {yy, xx}; }"
        : "=l"(r) : "l"(v));
    return r;
}
__device__ __forceinline__ u64 f2u(float a, float b) {
    u64 r; asm("mov.b64 %0, {%1, %2};" : "=l"(r) : "f"(a), "f"(b)); return r;
}
__device__ __forceinline__ float2 u2f(u64 v) {
    float2 r; asm("mov.b64 {%0, %1}, %2;" : "=f"(r.x), "=f"(r.y) : "l"(v)); return r;
}

// Packed complex 2x2 gate: re duplicated, im as (-im, im); g*v = re⊗v + imn⊗swap(v)
struct PG { u64 x00, y00, x01, y01, x10, y10, x11, y11; };
__device__ __forceinline__ PG mkpg(const float2* p) {
    PG g;
    g.x00 = pkdup(p[0].x); g.y00 = pkni(p[0].y);
    g.x01 = pkdup(p[1].x); g.y01 = pkni(p[1].y);
    g.x10 = pkdup(p[2].x); g.y10 = pkni(p[2].y);
    g.x11 = pkdup(p[3].x); g.y11 = pkni(p[3].y);
    return g;
}
__device__ __forceinline__ void bfly(const PG& g, u64& v0, u64& v1) {
    u64 s0 = swap64(v0), s1 = swap64(v1);
    u64 n0 = fma2(g.x00, v0, fma2(g.y00, s0, fma2(g.x01, v1, mul2(g.y01, s1))));
    u64 n1 = fma2(g.x10, v0, fma2(g.y10, s0, fma2(g.x11, v1, mul2(g.y11, s1))));
    v0 = n0; v1 = n1;
}

// smem bank swizzle: bijective (involution), makes exchange patterns conflict-free
__device__ __forceinline__ int swz(int n) { return n ^ ((n >> 4) & 0xF); }

// ring-of-CNOTs composed permutation (GF(2)-linear)
__device__ __forceinline__ int permf(int x) {
    #pragma unroll
    for (int c = NQ - 1; c >= 0; --c) {
        int t = (c + 1) % NQ;
        x ^= ((x >> (NQ - 1 - c)) & 1) << (NQ - 1 - t);
    }
    return x;
}

// ---------------- complex helper ----------------
__device__ __forceinline__ float2 cmul(float2 a, float2 b) {
    return make_float2(fmaf(a.x, b.x, -a.y * b.y), fmaf(a.x, b.y, a.y * b.x));
}

// ---------------- precompute fused gates ----------------
__global__ void precompute_kernel(const float* __restrict__ w, int ok) {
    int tid = threadIdx.x;
    if (tid >= 5 * NQ) return;
    float2* g = &d_gates[tid * 4];
    if (!ok || w == nullptr) {
        g[0] = make_float2(1.f, 0.f); g[1] = make_float2(0.f, 0.f);
        g[2] = make_float2(0.f, 0.f); g[3] = make_float2(1.f, 0.f);
        return;
    }
    int layer = tid / NQ, q = tid % NQ;
    const float WM = 0.6324555320336759f; // sqrt(2/5)
    float hx = w[3 * NQ * layer + q] * WM * 0.5f;
    float hy = w[3 * NQ * layer + NQ + q] * WM * 0.5f;
    float hz = w[3 * NQ * layer + 2 * NQ + q] * WM * 0.5f;
    float cx = cosf(hx), sx = sinf(hx);
    float cy = cosf(hy), sy = sinf(hy);
    float cz = cosf(hz), sz = sinf(hz);
    float2 m00 = make_float2( cy * cx,  sy * sx);
    float2 m01 = make_float2(-sy * cx, -cy * sx);
    float2 m10 = make_float2( sy * cx, -cy * sx);
    float2 m11 = make_float2( cy * cx, -sy * sx);
    float2 ezm = make_float2(cz, -sz);
    float2 ezp = make_float2(cz,  sz);
    g[0] = cmul(ezm, m00); g[1] = cmul(ezm, m01);
    g[2] = cmul(ezp, m10); g[3] = cmul(ezp, m11);
}

// ---------------- gate phases ----------------
// 3 register-qubit gates: g_b0 acts on reg bit0, g_b1 on bit1, g_b2 on bit2
__device__ __forceinline__ void reg3(u64 v[8], const float2* g_b0,
                                     const float2* g_b1, const float2* g_b2) {
    {
        PG g = mkpg(g_b0);
        bfly(g, v[0], v[1]); bfly(g, v[2], v[3]);
        bfly(g, v[4], v[5]); bfly(g, v[6], v[7]);
    }
    {
        PG g = mkpg(g_b1);
        bfly(g, v[0], v[2]); bfly(g, v[1], v[3]);
        bfly(g, v[4], v[6]); bfly(g, v[5], v[7]);
    }
    {
        PG g = mkpg(g_b2);
        bfly(g, v[0], v[4]); bfly(g, v[1], v[5]);
        bfly(g, v[2], v[6]); bfly(g, v[3], v[7]);
    }
}

// 5 lane-qubit gates via shfl: lane bit b = amplitude bit (3+b) = qubit (7-b)
__device__ __forceinline__ void shfl5(u64 v[8], const float2* gl, int l) {
    #pragma unroll
    for (int b = 0; b < 5; ++b) {
        const int m = 1 << b;
        const float2* gp = gl + (7 - b) * 4;
        const bool hi = (l >> b) & 1;
        PG g = mkpg(gp);
        u64 cmx = hi ? g.x11 : g.x00, cmy = hi ? g.y11 : g.y00;
        u64 cox = hi ? g.x10 : g.x01, coy = hi ? g.y10 : g.y01;
        #pragma unroll
        for (int j = 0; j < 8; ++j) {
            u64 o = __shfl_xor_sync(0xffffffffu, v[j], m);
            v[j] = fma2(cmx, v[j],
                   fma2(cmy, swap64(v[j]),
                   fma2(cox, o, mul2(coy, swap64(o)))));
        }
    }
}

// ---------------- core: applies U (gates already conj'ed for K1) ----------------
// Layout A: thread(w,l) reg j holds amplitude (w<<8)|(l<<3)|j     (reg bits = q10,q9,q8)
// Layout B: thread(w,l) reg j holds amplitude (j<<8)|(l<<3)|w     (reg bits = q2,q1,q0)
// Per layer: reg gates, shfl gates, ONE exchange (A<->B), other reg gates, perm.
// Enters in layout A, exits in layout A.
__device__ __forceinline__ void sim_core(u64 v[8], const float2* sg, int tid, u64* sm) {
    const int w = tid >> 5, l = tid & 31;
    const int baseA = (w << 8) | (l << 3);
    const int baseB = (l << 3) | w;
    const int pA = permf(baseA), pB = permf(baseB);
    const int pe0 = permf(1),   pe1 = permf(2),   pe2 = permf(4);
    const int pf0 = permf(256), pf1 = permf(512), pf2 = permf(1024);
    int pj0[8], pj8[8];
    #pragma unroll
    for (int j = 0; j < 8; ++j) {
        pj0[j] = ((j & 1) ? pe0 : 0) ^ ((j & 2) ? pe1 : 0) ^ ((j & 4) ? pe2 : 0);
        pj8[j] = ((j & 1) ? pf0 : 0) ^ ((j & 2) ? pf1 : 0) ^ ((j & 4) ? pf2 : 0);
    }

    for (int layer = 0; layer < 5; ++layer) {
        const float2* gl = sg + layer * 44;
        const bool inA = ((layer & 1) == 0);

        // gates on current layout's register qubits
        if (inA) reg3(v, gl + 40, gl + 36, gl + 32);   // q10,q9,q8
        else     reg3(v, gl + 8,  gl + 4,  gl + 0);    // q2,q1,q0

        // gates on lane qubits q3..q7
        shfl5(v, gl, l);

        // exchange: swap register bits <-> warp bits (A<->B)
        #pragma unroll
        for (int j = 0; j < 8; ++j)
            sm[swz(inA ? (baseA + j) : (baseB + (j << 8)))] = v[j];
        __syncthreads();
        #pragma unroll
        for (int j = 0; j < 8; ++j)
            v[j] = sm[swz(inA ? (baseB + (j << 8)) : (baseA + j))];
        __syncthreads();

        // gates on the flipped layout's register qubits
        if (inA) reg3(v, gl + 8,  gl + 4,  gl + 0);    // q2,q1,q0
        else     reg3(v, gl + 40, gl + 36, gl + 32);   // q10,q9,q8

        // ring-of-CNOTs permutation (gather), layers 0..3
        if (layer < 4) {
            const bool nowA = !inA;
            #pragma unroll
            for (int j = 0; j < 8; ++j)
                sm[swz(nowA ? (baseA + j) : (baseB + (j << 8)))] = v[j];
            __syncthreads();
            #pragma unroll
            for (int j = 0; j < 8; ++j)
                v[j] = sm[swz(nowA ? (pA ^ pj0[j]) : (pB ^ pj8[j]))];
            __syncthreads();
        }
    }

    // final flip B -> A (layer 4 ends in layout B)
    #pragma unroll
    for (int j = 0; j < 8; ++j) sm[swz(baseB + (j << 8))] = v[j];
    __syncthreads();
    #pragma unroll
    for (int j = 0; j < 8; ++j) v[j] = sm[swz(baseA + j)];
}

// ---------------- K1: B row k = conj(U) @ x_row_k -> d_B (coalesced) ----------------
__global__ void __launch_bounds__(256)
k1_rows(const float* __restrict__ x, int ok) {
    __shared__ u64   sm[DIM];
    __shared__ float2 sg[5 * NQ * 4];
    const int tid = threadIdx.x;
    const int vec = blockIdx.x;
    const int w = tid >> 5, l = tid & 31;
    const int baseA = (w << 8) | (l << 3);

    for (int i = tid; i < 5 * NQ * 4; i += 256) {
        float2 g = d_gates[i];
        g.y = -g.y;                       // conj(U)
        sg[i] = g;
    }

    u64 v[8];
    if (ok && x != nullptr) {
        const float4* src = (const float4*)(x + (size_t)vec * DIM + baseA);
        float4 a = src[0], b = src[1];
        v[0] = f2u(a.x, 0.f); v[1] = f2u(a.y, 0.f);
        v[2] = f2u(a.z, 0.f); v[3] = f2u(a.w, 0.f);
        v[4] = f2u(b.x, 0.f); v[5] = f2u(b.y, 0.f);
        v[6] = f2u(b.z, 0.f); v[7] = f2u(b.w, 0.f);
    } else {
        #pragma unroll
        for (int j = 0; j < 8; ++j) v[j] = 0ull;
    }
    __syncthreads();  // sg ready

    sim_core(v, sg, tid, sm);

    float4* dst = (float4*)(&d_B[(size_t)vec * DIM + baseA]);
    #pragma unroll
    for (int k = 0; k < 4; ++k) {
        float2 a = u2f(v[2 * k]), b = u2f(v[2 * k + 1]);
        dst[k] = make_float4(a.x, a.y, b.x, b.y);
    }
}

// ---------------- K2: out[:,col].real = real(U @ B_col) ----------------
__global__ void __launch_bounds__(256)
k2_cols(float* __restrict__ out, long long cap) {
    __shared__ u64   sm[DIM];
    __shared__ float2 sg[5 * NQ * 4];
    const int tid = threadIdx.x;
    const int col = blockIdx.x;
    const int w = tid >> 5, l = tid & 31;
    const int baseA = (w << 8) | (l << 3);

    for (int i = tid; i < 5 * NQ * 4; i += 256) sg[i] = d_gates[i]; // forward U

    u64 v[8];
    #pragma unroll
    for (int j = 0; j < 8; ++j) {
        float2 t = d_B[(size_t)(baseA + j) * DIM + col];
        v[j] = f2u(t.x, t.y);
    }
    __syncthreads();

    sim_core(v, sg, tid, sm);

    #pragma unroll
    for (int j = 0; j < 8; ++j) {
        long long idx = (long long)(baseA + j) * DIM + col;
        if (out != nullptr && idx < cap) out[idx] = u2f(v[j]).x;
    }
}

extern "C" void kernel_launch(void* const* d_in, const int* in_sizes, int n_in,
                              void* d_out, int out_size) {
    const float* x = nullptr;  int x_ok = 0;
    const float* w = nullptr;  int w_ok = 0;
    for (int i = 0; i < n_in; ++i) {
        if (in_sizes[i] >= DIM * DIM && !x) { x = (const float*)d_in[i]; x_ok = 1; }
        else if (in_sizes[i] >= 15 * NQ && in_sizes[i] < DIM * DIM && !w) {
            w = (const float*)d_in[i]; w_ok = 1;
        }
    }

    long long cap = (long long)out_size;
    if (cap > (long long)DIM * DIM) cap = (long long)DIM * DIM;

    precompute_kernel<<<1, 64>>>(w, w_ok);
    k1_rows<<<DIM, 256>>>(x, x_ok);               // d_B := B = Xc U^H (rows)
    k2_cols<<<DIM, 256>>>((float*)d_out, cap);    // out := real(U @ B) columns
}